// round 16
// baseline (speedup 1.0000x reference)
#include <cuda_runtime.h>
#include <cuda_fp16.h>
#include <cstdint>
#include <math.h>

// Problem constants
#define B_      4
#define S_      4096
#define DIN     1024
#define NC      1024
#define N1      2048
#define M_      (B_*S_)         // 16384
#define LANES   (B_*NC)         // 4096
#define NCHUNK  64
#define LC      (S_/NCHUNK)     // 64
#define KP      512             // k-pairs per row (1024 k / 2)

// ---------------- scratch (static device globals) ----------------
__device__ uint32_t g_W1T[(size_t)N1 * KP];       // packed weights [n][k] halves (u32 = kpair)
__device__ uint32_t g_WgT[(size_t)NC * KP];       // gate weights [n][k] halves
__device__ uint32_t g_X16[(size_t)M_ * KP];       // x pre-converted to fp16, [m][kpair]
__device__ uint32_t g_H16[(size_t)M_ * KP];       // h pre-converted to fp16, [m][kpair]
__device__ float    g_b1[N1];
__device__ float    g_Y[(size_t)M_ * N1];         // interleaved (a,b) pairs for the scan
__device__ float    g_h[(size_t)M_ * NC];         // fp32 h (epilogue gating)
__device__ float4   g_AggV[NCHUNK * LANES / 2];   // per-(chunk,lane) aggregates, 2 lanes per float4
__device__ float    g_Carry[NCHUNK * LANES];

__device__ __forceinline__ float sigmoidf_(float x) { return 1.0f / (1.0f + __expf(-x)); }
__device__ __forceinline__ uint32_t packh2(float lo, float hi) {
    __half2 h = __floats2half2_rn(lo, hi);
    return *(uint32_t*)&h;
}
__device__ __forceinline__ uint32_t smem_u32(const void* p) {
    uint32_t a;
    asm("{ .reg .u64 t; cvta.to.shared.u64 t, %1; cvt.u32.u64 %0, t; }" : "=r"(a) : "l"(p));
    return a;
}
__device__ __forceinline__ void ldsm_x4(uint32_t r[4], uint32_t addr) {
    asm volatile("ldmatrix.sync.aligned.m8n8.x4.shared.b16 {%0,%1,%2,%3}, [%4];"
                 : "=r"(r[0]), "=r"(r[1]), "=r"(r[2]), "=r"(r[3]) : "r"(addr));
}
__device__ __forceinline__ void mma_f16(float c[4],
                                        uint32_t a0, uint32_t a1, uint32_t a2, uint32_t a3,
                                        uint32_t b0, uint32_t b1) {
    asm volatile(
        "mma.sync.aligned.m16n8k16.row.col.f32.f16.f16.f32 "
        "{%0,%1,%2,%3}, {%4,%5,%6,%7}, {%8,%9}, {%0,%1,%2,%3};"
        : "+f"(c[0]), "+f"(c[1]), "+f"(c[2]), "+f"(c[3])
        : "r"(a0), "r"(a1), "r"(a2), "r"(a3), "r"(b0), "r"(b1));
}
__device__ __forceinline__ void cp_async16(uint32_t saddr, const void* gaddr) {
    asm volatile("cp.async.cg.shared.global [%0], [%1], 16;" :: "r"(saddr), "l"(gaddr));
}
#define CP_COMMIT() asm volatile("cp.async.commit_group;" ::: "memory")
#define CP_WAITG(n) asm volatile("cp.async.wait_group %0;" :: "n"(n) : "memory")

// ---------------- packing kernels ----------------
__global__ void pack_w1_all(const float* __restrict__ Wzf, const float* __restrict__ Whf,
                            const float* __restrict__ Wzs, const float* __restrict__ Whs) {
    __shared__ float sm[32][33];
    const float* src;
    int nOff;
    switch (blockIdx.z) {
        case 0: src = Wzf; nOff = 0;    break;
        case 1: src = Whf; nOff = 1;    break;
        case 2: src = Wzs; nOff = 1024; break;
        default: src = Whs; nOff = 1025; break;
    }
    int c0 = blockIdx.x * 32;
    int k0 = blockIdx.y * 32;
    int tx = threadIdx.x, ty = threadIdx.y;
    sm[tx][ty] = src[(size_t)(k0 + tx) * 512 + c0 + ty];   // sm[k][c]
    __syncthreads();
    if (tx < 16) {
        int n = nOff + 2 * (c0 + ty);
        g_W1T[(size_t)n * KP + (k0 >> 1) + tx] = packh2(sm[2 * tx][ty], sm[2 * tx + 1][ty]);
    }
}

__global__ void pack_wg(const float* __restrict__ Wg) {
    __shared__ float sm[32][33];
    int c0 = blockIdx.x * 32;
    int k0 = blockIdx.y * 32;
    int tx = threadIdx.x, ty = threadIdx.y;
    sm[tx][ty] = Wg[(size_t)(k0 + tx) * 1024 + c0 + ty];
    __syncthreads();
    if (tx < 16) {
        int n = c0 + ty;
        g_WgT[(size_t)n * KP + (k0 >> 1) + tx] = packh2(sm[2 * tx][ty], sm[2 * tx + 1][ty]);
    }
}

// x -> fp16 (coalesced), plus bias packing folded in
__global__ void convert_x16(const float4* __restrict__ x4,
                            const float* __restrict__ bzf, const float* __restrict__ bhf,
                            const float* __restrict__ bzs, const float* __restrict__ bhs) {
    int idx = blockIdx.x * 256 + threadIdx.x;
    float4 v = x4[idx];
    ((uint2*)g_X16)[idx] = make_uint2(packh2(v.x, v.y), packh2(v.z, v.w));
    if (idx < N1) {
        int c = idx >> 1, hp = idx & 1;
        float b;
        if (c < 512) b = hp ? bhf[c]       : bzf[c];
        else         b = hp ? bhs[c - 512] : bzs[c - 512];
        g_b1[idx] = b;
    }
}

// ---------------- fp16 GEMM: 128x64 CTA, 256 thr, 8 warps (32x32 tiles), 3 CTAs/SM ----
// 6-stage cp.async ring: stage = A 8KB + B 4KB = 12KB; 6 stages = 72KB -> 3 CTAs/SM.
// Pair protocol (proven in R14): WAITG(2) -> __syncthreads -> issue 2 -> compute 2.
// Row layout [row][32 halves]; 16B-chunk swizzle: phys_chunk = chunk ^ ((row>>1)&3).
#define STG 12288
#define NSTAGE 6

template <int MODE>   // 1 = GEMM1 (scan-coeff epilogue), 2 = GEMM2 (gated-output epilogue)
__device__ __forceinline__ void gemm_core(const uint32_t* __restrict__ A16,
                                          const uint32_t* __restrict__ BT,
                                          const float* __restrict__ bias,
                                          float* __restrict__ Out) {
    extern __shared__ __align__(16) uint8_t smem[];

    const int tid  = threadIdx.x;
    const int lane = tid & 31, w = tid >> 5;          // w: 0..7
    const int g = lane >> 2, t = lane & 3;
    const int wm = (w & 3) * 32, wn = (w >> 2) * 32;  // 4(M) x 2(N) warp grid, 32x32 tiles
    const int bm = blockIdx.y * 128, bn = blockIdx.x * 64;

    const uint32_t* Ag = A16 + (size_t)bm * KP;
    const uint32_t* Bg = BT  + (size_t)bn * KP;

    const uint32_t u0 = smem_u32(smem);

    // ---- cp.async mapping ----
    // A: 128 rows x 4 chunks = 512 slots, 2 per thread (row = tid&127, chunks aC0, aC0+1)
    // B: 64 rows x 4 chunks = 256 slots, 1 per thread (row = tid&63, chunk = tid>>6)
    const int aRow = tid & 127;
    const int aC0  = (tid >> 7) << 1;
    const int sxa  = (aRow >> 1) & 3;
    const uint32_t sA0 = aRow * 64 + (((aC0)     ^ sxa) << 4);
    const uint32_t sA1 = aRow * 64 + (((aC0 + 1) ^ sxa) << 4);
    const int bRow = tid & 63;
    const int bC   = tid >> 6;
    const uint32_t sB0 = 8192 + bRow * 64 + ((bC ^ ((bRow >> 1) & 3)) << 4);

    const uint32_t* cpA0 = Ag + (size_t)aRow * KP + aC0 * 4;
    const uint32_t* cpA1 = cpA0 + 4;
    const uint32_t* cpB0 = Bg + (size_t)bRow * KP + bC * 4;

    // ---- precomputed ldmatrix offsets (loop-invariant) ----
    const int ro = lane & 15, hi = lane >> 4;
    uint32_t offA[2][2], offB[2][2];
#pragma unroll
    for (int sb = 0; sb < 2; sb++) {
        const int ch = sb * 2 + hi;
#pragma unroll
        for (int q = 0; q < 2; q++) {
            int rowA = wm + q * 16 + ro;
            offA[sb][q] = rowA * 64 + ((ch ^ ((rowA >> 1) & 3)) << 4);
            int rowB = wn + q * 16 + ro;
            offB[sb][q] = 8192 + rowB * 64 + ((ch ^ ((rowB >> 1) & 3)) << 4);
        }
    }

    float acc[2][4][4];
#pragma unroll
    for (int i = 0; i < 2; i++)
#pragma unroll
        for (int j = 0; j < 4; j++)
#pragma unroll
            for (int q = 0; q < 4; q++) acc[i][j][q] = 0.0f;

    auto issue = [&](int buf) {
        const uint32_t d = u0 + (uint32_t)buf * STG;
        cp_async16(d + sA0, cpA0);
        cp_async16(d + sA1, cpA1);
        cp_async16(d + sB0, cpB0);
        cpA0 += 16; cpA1 += 16; cpB0 += 16;
        CP_COMMIT();
    };

    auto compute = [&](int buf) {
        const uint32_t base = u0 + (uint32_t)buf * STG;
#pragma unroll
        for (int sb = 0; sb < 2; sb++) {
            uint32_t af[2][4], bf[2][4];
#pragma unroll
            for (int q = 0; q < 2; q++) ldsm_x4(af[q], base + offA[sb][q]);
#pragma unroll
            for (int q = 0; q < 2; q++) ldsm_x4(bf[q], base + offB[sb][q]);
#pragma unroll
            for (int mt = 0; mt < 2; mt++)
#pragma unroll
                for (int nt = 0; nt < 4; nt++) {
                    int np = nt >> 1, q = nt & 1;
                    mma_f16(acc[mt][nt], af[mt][0], af[mt][1], af[mt][2], af[mt][3],
                            bf[np][q], bf[np][2 + q]);
                }
        }
    };

    // prologue: stages 0..3 into buffers 0..3 (pending = 4 groups per thread)
    issue(0); issue(1); issue(2); issue(3);

    int cb = 0;   // buffer of the stage being computed
    int ib = 4;   // next buffer to fill
    // pairs kt = 0..24: wait -> sync -> issue kt+4, kt+5 -> compute kt, kt+1
    for (int kt = 0; kt < 26; kt += 2) {
        CP_WAITG(2);          // my stages kt, kt+1 landed
        __syncthreads();      // everyone's landed; prev pair's computes done
        issue(ib); ib = (ib == NSTAGE - 1) ? 0 : ib + 1;
        issue(ib); ib = (ib == NSTAGE - 1) ? 0 : ib + 1;
        compute(cb); cb = (cb == NSTAGE - 1) ? 0 : cb + 1;
        compute(cb); cb = (cb == NSTAGE - 1) ? 0 : cb + 1;
    }
    // pair kt=26: issue stages 30, 31; compute 26, 27
    CP_WAITG(2);
    __syncthreads();
    issue(ib); ib = (ib == NSTAGE - 1) ? 0 : ib + 1;
    issue(ib);
    compute(cb); cb = (cb == NSTAGE - 1) ? 0 : cb + 1;
    compute(cb); cb = (cb == NSTAGE - 1) ? 0 : cb + 1;
    // pair kt=28: compute 28, 29
    CP_WAITG(2);
    __syncthreads();
    compute(cb); cb = (cb == NSTAGE - 1) ? 0 : cb + 1;
    compute(cb); cb = (cb == NSTAGE - 1) ? 0 : cb + 1;
    // pair kt=30: compute 30, 31
    CP_WAITG(0);
    __syncthreads();
    compute(cb); cb = (cb == NSTAGE - 1) ? 0 : cb + 1;
    compute(cb);

    // ---------------- epilogue ----------------
    const int NOUT = (MODE == 1) ? N1 : NC;
#pragma unroll
    for (int mt = 0; mt < 2; mt++) {
#pragma unroll
        for (int nt = 0; nt < 4; nt++) {
            int row = bm + wm + mt * 16 + g;
            int col = bn + wn + nt * 8 + t * 2;       // even: one (z, h~) pair
            float2 bb = *(const float2*)&bias[col];
            const float* a4 = acc[mt][nt];
            if (MODE == 1) {
                float z0 = sigmoidf_(a4[0] + bb.x);
                float h0 = a4[1] + bb.y;
                *(float2*)&Out[(size_t)row * NOUT + col] = make_float2(1.0f - z0, z0 * h0);
                float z1 = sigmoidf_(a4[2] + bb.x);
                float h1 = a4[3] + bb.y;
                *(float2*)&Out[(size_t)(row + 8) * NOUT + col] = make_float2(1.0f - z1, z1 * h1);
            } else {
                float2 hv0 = *(const float2*)&g_h[(size_t)row * NC + col];
                *(float2*)&Out[(size_t)row * NOUT + col] =
                    make_float2(hv0.x * sigmoidf_(a4[0] + bb.x),
                                hv0.y * sigmoidf_(a4[1] + bb.y));
                float2 hv1 = *(const float2*)&g_h[(size_t)(row + 8) * NC + col];
                *(float2*)&Out[(size_t)(row + 8) * NOUT + col] =
                    make_float2(hv1.x * sigmoidf_(a4[2] + bb.x),
                                hv1.y * sigmoidf_(a4[3] + bb.y));
            }
        }
    }
}

__global__ void __launch_bounds__(256, 3) gemm1_mma() {
    gemm_core<1>(g_X16, g_W1T, g_b1, g_Y);
}
__global__ void __launch_bounds__(256, 3) gemm2_mma(const float* __restrict__ bg,
                                                    float* __restrict__ out) {
    gemm_core<2>(g_H16, g_WgT, bg, out);
}

// ---------------- scan (3-phase chunked, vectorized) ----------------
__global__ __launch_bounds__(256) void scan_phase1() {
    int p = blockIdx.x * 256 + threadIdx.x;   // 0..2047 channel-pairs
    int j = blockIdx.y;
    int b = p >> 9;
    int c = (p & 511) * 2;                    // even channel
    const float4* Y4 = (const float4*)g_Y;    // row = 512 float4
    size_t base = (size_t)(b * S_ + j * LC) * 512 + (c >> 1);
    float A0 = 1.0f, H0 = 0.0f, A1 = 1.0f, H1 = 0.0f;
#pragma unroll 8
    for (int t = 0; t < LC; t++) {
        float4 v = Y4[base + (size_t)t * 512];
        A0 *= v.x; H0 = fmaf(v.x, H0, v.y);
        A1 *= v.z; H1 = fmaf(v.z, H1, v.w);
    }
    int lane = b * 1024 + c;
    g_AggV[(j * LANES + lane) >> 1] = make_float4(A0, H0, A1, H1);
}

// batched-MLP sequential combine: 4 batches of 16 independent loads, then register scan
__global__ __launch_bounds__(256) void scan_phase2() {
    int lane = blockIdx.x * blockDim.x + threadIdx.x;
    const float2* Agg2 = (const float2*)g_AggV;
    float carry = 0.0f;
#pragma unroll
    for (int b4 = 0; b4 < 4; b4++) {
        float2 e[16];
#pragma unroll
        for (int i = 0; i < 16; i++)
            e[i] = Agg2[(b4 * 16 + i) * LANES + lane];
#pragma unroll
        for (int i = 0; i < 16; i++) {
            g_Carry[(b4 * 16 + i) * LANES + lane] = carry;
            carry = fmaf(e[i].x, carry, e[i].y);
        }
    }
}

__global__ __launch_bounds__(256) void scan_phase3() {
    int p = blockIdx.x * 256 + threadIdx.x;
    int j = blockIdx.y;
    int b = p >> 9;
    int c = (p & 511) * 2;
    const float4* Y4 = (const float4*)g_Y;
    size_t m0 = (size_t)(b * S_ + j * LC);
    size_t base = m0 * 512 + (c >> 1);
    int lane = b * 1024 + c;
    float2 carry = *(const float2*)&g_Carry[j * LANES + lane];
    float H0 = carry.x, H1 = carry.y;
    __half* H16 = (__half*)g_H16;
#pragma unroll 8
    for (int t = 0; t < LC; t++) {
        float4 v = Y4[base + (size_t)t * 512];
        H0 = fmaf(v.x, H0, v.y);
        H1 = fmaf(v.z, H1, v.w);
        size_t m = m0 + t;
        *(float2*)&g_h[m * NC + c] = make_float2(H0, H1);
        *(__half2*)(H16 + m * NC + c) = __floats2half2_rn(H0, H1);
    }
}

// ---------------- launch ----------------
// gemm1_mma is my 4th launch (global idx 5 for the ncu -s 5 -c 1 capture).
extern "C" void kernel_launch(void* const* d_in, const int* in_sizes, int n_in,
                              void* d_out, int out_size) {
    const float* x   = (const float*)d_in[0];
    const float* Wzf = (const float*)d_in[1];
    const float* bzf = (const float*)d_in[2];
    const float* Whf = (const float*)d_in[3];
    const float* bhf = (const float*)d_in[4];
    const float* Wzs = (const float*)d_in[5];
    const float* bzs = (const float*)d_in[6];
    const float* Whs = (const float*)d_in[7];
    const float* bhs = (const float*)d_in[8];
    const float* Wg  = (const float*)d_in[9];
    const float* bg  = (const float*)d_in[10];
    float* out = (float*)d_out;

    cudaFuncSetAttribute(gemm1_mma, cudaFuncAttributeMaxDynamicSharedMemorySize, NSTAGE * STG);
    cudaFuncSetAttribute(gemm2_mma, cudaFuncAttributeMaxDynamicSharedMemorySize, NSTAGE * STG);

    dim3 tb(32, 32);
    pack_w1_all<<<dim3(16, 32, 4), tb>>>(Wzf, Whf, Wzs, Whs);
    pack_wg<<<dim3(32, 32), tb>>>(Wg);
    convert_x16<<<(M_ * DIN / 4) / 256, 256>>>((const float4*)x, bzf, bhf, bzs, bhs);

    gemm1_mma<<<dim3(N1 / 64, M_ / 128), 256, NSTAGE * STG>>>();

    scan_phase1<<<dim3(8, NCHUNK), 256>>>();
    scan_phase2<<<LANES / 256, 256>>>();
    scan_phase3<<<dim3(8, NCHUNK), 256>>>();

    gemm2_mma<<<dim3(NC / 64, M_ / 128), 256, NSTAGE * STG>>>(bg, out);
}

// round 17
// speedup vs baseline: 1.7546x; 1.7546x over previous
#include <cuda_runtime.h>
#include <cuda_fp16.h>
#include <cstdint>
#include <math.h>

// Problem constants
#define B_      4
#define S_      4096
#define DIN     1024
#define NC      1024
#define N1      2048
#define M_      (B_*S_)         // 16384
#define LANES   (B_*NC)         // 4096
#define NCHUNK  64
#define LC      (S_/NCHUNK)     // 64
#define KP      512             // k-pairs per row (1024 k / 2)

// ---------------- scratch (static device globals) ----------------
__device__ uint32_t g_W1T[(size_t)N1 * KP];       // packed weights [n][k] halves (u32 = kpair)
__device__ uint32_t g_WgT[(size_t)NC * KP];       // gate weights [n][k] halves
__device__ uint32_t g_X16[(size_t)M_ * KP];       // x pre-converted to fp16, [m][kpair]
__device__ uint32_t g_H16[(size_t)M_ * KP];       // h in fp16, [m][kpair] (gemm2 A operand AND gating source)
__device__ float    g_b1[N1];
__device__ float    g_Y[(size_t)M_ * N1];         // interleaved (a,b) pairs for the scan
__device__ float4   g_AggV[NCHUNK * LANES / 2];   // per-(chunk,lane) aggregates, 2 lanes per float4
__device__ float    g_Carry[NCHUNK * LANES];

__device__ __forceinline__ float sigmoidf_(float x) { return 1.0f / (1.0f + __expf(-x)); }
__device__ __forceinline__ uint32_t packh2(float lo, float hi) {
    __half2 h = __floats2half2_rn(lo, hi);
    return *(uint32_t*)&h;
}
__device__ __forceinline__ uint32_t smem_u32(const void* p) {
    uint32_t a;
    asm("{ .reg .u64 t; cvta.to.shared.u64 t, %1; cvt.u32.u64 %0, t; }" : "=r"(a) : "l"(p));
    return a;
}
__device__ __forceinline__ void ldsm_x4(uint32_t r[4], uint32_t addr) {
    asm volatile("ldmatrix.sync.aligned.m8n8.x4.shared.b16 {%0,%1,%2,%3}, [%4];"
                 : "=r"(r[0]), "=r"(r[1]), "=r"(r[2]), "=r"(r[3]) : "r"(addr));
}
__device__ __forceinline__ void mma_f16(float c[4],
                                        uint32_t a0, uint32_t a1, uint32_t a2, uint32_t a3,
                                        uint32_t b0, uint32_t b1) {
    asm volatile(
        "mma.sync.aligned.m16n8k16.row.col.f32.f16.f16.f32 "
        "{%0,%1,%2,%3}, {%4,%5,%6,%7}, {%8,%9}, {%0,%1,%2,%3};"
        : "+f"(c[0]), "+f"(c[1]), "+f"(c[2]), "+f"(c[3])
        : "r"(a0), "r"(a1), "r"(a2), "r"(a3), "r"(b0), "r"(b1));
}
__device__ __forceinline__ void cp_async16(uint32_t saddr, const void* gaddr) {
    asm volatile("cp.async.cg.shared.global [%0], [%1], 16;" :: "r"(saddr), "l"(gaddr));
}
#define CP_COMMIT() asm volatile("cp.async.commit_group;" ::: "memory")
#define CP_WAITG(n) asm volatile("cp.async.wait_group %0;" :: "n"(n) : "memory")

// ---------------- packing kernels ----------------
__global__ void pack_w1_all(const float* __restrict__ Wzf, const float* __restrict__ Whf,
                            const float* __restrict__ Wzs, const float* __restrict__ Whs) {
    __shared__ float sm[32][33];
    const float* src;
    int nOff;
    switch (blockIdx.z) {
        case 0: src = Wzf; nOff = 0;    break;
        case 1: src = Whf; nOff = 1;    break;
        case 2: src = Wzs; nOff = 1024; break;
        default: src = Whs; nOff = 1025; break;
    }
    int c0 = blockIdx.x * 32;
    int k0 = blockIdx.y * 32;
    int tx = threadIdx.x, ty = threadIdx.y;
    sm[tx][ty] = src[(size_t)(k0 + tx) * 512 + c0 + ty];   // sm[k][c]
    __syncthreads();
    if (tx < 16) {
        int n = nOff + 2 * (c0 + ty);
        g_W1T[(size_t)n * KP + (k0 >> 1) + tx] = packh2(sm[2 * tx][ty], sm[2 * tx + 1][ty]);
    }
}

__global__ void pack_wg(const float* __restrict__ Wg) {
    __shared__ float sm[32][33];
    int c0 = blockIdx.x * 32;
    int k0 = blockIdx.y * 32;
    int tx = threadIdx.x, ty = threadIdx.y;
    sm[tx][ty] = Wg[(size_t)(k0 + tx) * 1024 + c0 + ty];
    __syncthreads();
    if (tx < 16) {
        int n = c0 + ty;
        g_WgT[(size_t)n * KP + (k0 >> 1) + tx] = packh2(sm[2 * tx][ty], sm[2 * tx + 1][ty]);
    }
}

// x -> fp16 (coalesced), plus bias packing folded in
__global__ void convert_x16(const float4* __restrict__ x4,
                            const float* __restrict__ bzf, const float* __restrict__ bhf,
                            const float* __restrict__ bzs, const float* __restrict__ bhs) {
    int idx = blockIdx.x * 256 + threadIdx.x;
    float4 v = x4[idx];
    ((uint2*)g_X16)[idx] = make_uint2(packh2(v.x, v.y), packh2(v.z, v.w));
    if (idx < N1) {
        int c = idx >> 1, hp = idx & 1;
        float b;
        if (c < 512) b = hp ? bhf[c]       : bzf[c];
        else         b = hp ? bhs[c - 512] : bzs[c - 512];
        g_b1[idx] = b;
    }
}

// ---------------- fp16 GEMM (exact R14 config): 128x128 CTA, 256 thr, 8 warps (64x32) ----
// 6-stage cp.async ring (96KB dynamic smem), ONE __syncthreads per TWO stages.
// Pair protocol: WAITG(2) -> __syncthreads -> issue 2 -> compute 2.
#define STG 16384
#define NSTAGE 6

template <int MODE>   // 1 = GEMM1 (scan-coeff epilogue), 2 = GEMM2 (gated-output epilogue)
__device__ __forceinline__ void gemm_core(const uint32_t* __restrict__ A16,
                                          const uint32_t* __restrict__ BT,
                                          const float* __restrict__ bias,
                                          float* __restrict__ Out) {
    extern __shared__ __align__(16) uint8_t smem[];

    const int tid  = threadIdx.x;
    const int lane = tid & 31, w = tid >> 5;          // w: 0..7
    const int g = lane >> 2, t = lane & 3;
    const int wm = (w & 1) * 64, wn = (w >> 1) * 32;  // 2(M) x 4(N) warp grid, 64x32 tiles
    const int bm = blockIdx.y * 128, bn = blockIdx.x * 128;
    const int mrow = tid >> 2;     // 0..63 (+64)
    const int kq   = tid & 3;      // 16B chunk within the 64B row-stage

    const uint32_t* Ag = A16 + (size_t)bm * KP;
    const uint32_t* Bg = BT  + (size_t)bn * KP;

    const int stChunk = ((kq ^ ((mrow >> 1) & 3)) << 4);
    const uint32_t u0 = smem_u32(smem);

    // ---- precomputed ldmatrix offsets (loop-invariant) ----
    const int ro = lane & 15, hi = lane >> 4;
    uint32_t offA[2][4], offB[2][2];
#pragma unroll
    for (int sb = 0; sb < 2; sb++) {
        const int ch = sb * 2 + hi;
#pragma unroll
        for (int q = 0; q < 4; q++) {
            int rowA = wm + q * 16 + ro;
            offA[sb][q] = rowA * 64 + ((ch ^ ((rowA >> 1) & 3)) << 4);
        }
#pragma unroll
        for (int q = 0; q < 2; q++) {
            int rowB = wn + q * 16 + ro;
            offB[sb][q] = 8192 + rowB * 64 + ((ch ^ ((rowB >> 1) & 3)) << 4);
        }
    }

    // ---- cp.async pointers (advance +16 per stage) ----
    const uint32_t* cpA0 = Ag + (size_t)mrow * KP + kq * 4;
    const uint32_t* cpA1 = cpA0 + (size_t)64 * KP;
    const uint32_t* cpB0 = Bg + (size_t)mrow * KP + kq * 4;
    const uint32_t* cpB1 = cpB0 + (size_t)64 * KP;
    const uint32_t sA0 = mrow * 64 + stChunk;
    const uint32_t sA1 = (mrow + 64) * 64 + stChunk;

    float acc[4][4][4];
#pragma unroll
    for (int i = 0; i < 4; i++)
#pragma unroll
        for (int j = 0; j < 4; j++)
#pragma unroll
            for (int q = 0; q < 4; q++) acc[i][j][q] = 0.0f;

    auto issue = [&](int buf) {
        const uint32_t d = u0 + (uint32_t)buf * STG;
        cp_async16(d + sA0,        cpA0);
        cp_async16(d + sA1,        cpA1);
        cp_async16(d + 8192 + sA0, cpB0);
        cp_async16(d + 8192 + sA1, cpB1);
        cpA0 += 16; cpA1 += 16; cpB0 += 16; cpB1 += 16;
        CP_COMMIT();
    };

    auto compute = [&](int buf) {
        const uint32_t base = u0 + (uint32_t)buf * STG;
#pragma unroll
        for (int sb = 0; sb < 2; sb++) {
            uint32_t af[4][4], bf[2][4];
#pragma unroll
            for (int q = 0; q < 4; q++) ldsm_x4(af[q], base + offA[sb][q]);
#pragma unroll
            for (int q = 0; q < 2; q++) ldsm_x4(bf[q], base + offB[sb][q]);
#pragma unroll
            for (int mt = 0; mt < 4; mt++)
#pragma unroll
                for (int nt = 0; nt < 4; nt++) {
                    int np = nt >> 1, q = nt & 1;
                    mma_f16(acc[mt][nt], af[mt][0], af[mt][1], af[mt][2], af[mt][3],
                            bf[np][q], bf[np][2 + q]);
                }
        }
    };

    // prologue: stages 0..3 into buffers 0..3 (pending = 4 groups per thread)
    issue(0); issue(1); issue(2); issue(3);

    int cb = 0;   // buffer of the stage being computed
    int ib = 4;   // next buffer to fill
    for (int kt = 0; kt < 26; kt += 2) {
        CP_WAITG(2);          // my stages kt, kt+1 landed
        __syncthreads();      // everyone's landed; prev pair's computes done
        issue(ib); ib = (ib == NSTAGE - 1) ? 0 : ib + 1;
        issue(ib); ib = (ib == NSTAGE - 1) ? 0 : ib + 1;
        compute(cb); cb = (cb == NSTAGE - 1) ? 0 : cb + 1;
        compute(cb); cb = (cb == NSTAGE - 1) ? 0 : cb + 1;
    }
    // pair kt=26: issue stages 30, 31; compute 26, 27
    CP_WAITG(2);
    __syncthreads();
    issue(ib); ib = (ib == NSTAGE - 1) ? 0 : ib + 1;
    issue(ib);
    compute(cb); cb = (cb == NSTAGE - 1) ? 0 : cb + 1;
    compute(cb); cb = (cb == NSTAGE - 1) ? 0 : cb + 1;
    // pair kt=28
    CP_WAITG(2);
    __syncthreads();
    compute(cb); cb = (cb == NSTAGE - 1) ? 0 : cb + 1;
    compute(cb); cb = (cb == NSTAGE - 1) ? 0 : cb + 1;
    // pair kt=30
    CP_WAITG(0);
    __syncthreads();
    compute(cb); cb = (cb == NSTAGE - 1) ? 0 : cb + 1;
    compute(cb);

    // ---------------- epilogue ----------------
    const int NOUT = (MODE == 1) ? N1 : NC;
    const __half* H16 = (const __half*)g_H16;
#pragma unroll
    for (int mt = 0; mt < 4; mt++) {
#pragma unroll
        for (int nt = 0; nt < 4; nt++) {
            int row = bm + wm + mt * 16 + g;
            int col = bn + wn + nt * 8 + t * 2;       // even: one (z, h~) pair
            float2 bb = *(const float2*)&bias[col];
            const float* a4 = acc[mt][nt];
            if (MODE == 1) {
                float z0 = sigmoidf_(a4[0] + bb.x);
                float h0 = a4[1] + bb.y;
                *(float2*)&Out[(size_t)row * NOUT + col] = make_float2(1.0f - z0, z0 * h0);
                float z1 = sigmoidf_(a4[2] + bb.x);
                float h1 = a4[3] + bb.y;
                *(float2*)&Out[(size_t)(row + 8) * NOUT + col] = make_float2(1.0f - z1, z1 * h1);
            } else {
                float2 hv0 = __half22float2(*(const __half2*)(H16 + (size_t)row * NC + col));
                *(float2*)&Out[(size_t)row * NOUT + col] =
                    make_float2(hv0.x * sigmoidf_(a4[0] + bb.x),
                                hv0.y * sigmoidf_(a4[1] + bb.y));
                float2 hv1 = __half22float2(*(const __half2*)(H16 + (size_t)(row + 8) * NC + col));
                *(float2*)&Out[(size_t)(row + 8) * NOUT + col] =
                    make_float2(hv1.x * sigmoidf_(a4[2] + bb.x),
                                hv1.y * sigmoidf_(a4[3] + bb.y));
            }
        }
    }
}

__global__ void __launch_bounds__(256, 2) gemm1_mma() {
    gemm_core<1>(g_X16, g_W1T, g_b1, g_Y);
}
__global__ void __launch_bounds__(256, 2) gemm2_mma(const float* __restrict__ bg,
                                                    float* __restrict__ out) {
    gemm_core<2>(g_H16, g_WgT, bg, out);
}

// ---------------- scan (3-phase chunked, vectorized) ----------------
__global__ __launch_bounds__(256) void scan_phase1() {
    int p = blockIdx.x * 256 + threadIdx.x;   // 0..2047 channel-pairs
    int j = blockIdx.y;
    int b = p >> 9;
    int c = (p & 511) * 2;                    // even channel
    const float4* Y4 = (const float4*)g_Y;    // row = 512 float4
    size_t base = (size_t)(b * S_ + j * LC) * 512 + (c >> 1);
    float A0 = 1.0f, H0 = 0.0f, A1 = 1.0f, H1 = 0.0f;
#pragma unroll 8
    for (int t = 0; t < LC; t++) {
        float4 v = Y4[base + (size_t)t * 512];
        A0 *= v.x; H0 = fmaf(v.x, H0, v.y);
        A1 *= v.z; H1 = fmaf(v.z, H1, v.w);
    }
    int lane = b * 1024 + c;
    g_AggV[(j * LANES + lane) >> 1] = make_float4(A0, H0, A1, H1);
}

// batched-MLP sequential combine: 4 batches of 16 independent loads, then register scan
__global__ __launch_bounds__(256) void scan_phase2() {
    int lane = blockIdx.x * blockDim.x + threadIdx.x;
    const float2* Agg2 = (const float2*)g_AggV;
    float carry = 0.0f;
#pragma unroll
    for (int b4 = 0; b4 < 4; b4++) {
        float2 e[16];
#pragma unroll
        for (int i = 0; i < 16; i++)
            e[i] = Agg2[(b4 * 16 + i) * LANES + lane];
#pragma unroll
        for (int i = 0; i < 16; i++) {
            g_Carry[(b4 * 16 + i) * LANES + lane] = carry;
            carry = fmaf(e[i].x, carry, e[i].y);
        }
    }
}

__global__ __launch_bounds__(256) void scan_phase3() {
    int p = blockIdx.x * 256 + threadIdx.x;
    int j = blockIdx.y;
    int b = p >> 9;
    int c = (p & 511) * 2;
    const float4* Y4 = (const float4*)g_Y;
    size_t m0 = (size_t)(b * S_ + j * LC);
    size_t base = m0 * 512 + (c >> 1);
    int lane = b * 1024 + c;
    float2 carry = *(const float2*)&g_Carry[j * LANES + lane];
    float H0 = carry.x, H1 = carry.y;
    __half* H16 = (__half*)g_H16;
#pragma unroll 8
    for (int t = 0; t < LC; t++) {
        float4 v = Y4[base + (size_t)t * 512];
        H0 = fmaf(v.x, H0, v.y);
        H1 = fmaf(v.z, H1, v.w);
        *(__half2*)(H16 + (m0 + t) * NC + c) = __floats2half2_rn(H0, H1);
    }
}

// ---------------- launch ----------------
// gemm1_mma is my 4th launch (global idx 5 for the ncu -s 5 -c 1 capture).
extern "C" void kernel_launch(void* const* d_in, const int* in_sizes, int n_in,
                              void* d_out, int out_size) {
    const float* x   = (const float*)d_in[0];
    const float* Wzf = (const float*)d_in[1];
    const float* bzf = (const float*)d_in[2];
    const float* Whf = (const float*)d_in[3];
    const float* bhf = (const float*)d_in[4];
    const float* Wzs = (const float*)d_in[5];
    const float* bzs = (const float*)d_in[6];
    const float* Whs = (const float*)d_in[7];
    const float* bhs = (const float*)d_in[8];
    const float* Wg  = (const float*)d_in[9];
    const float* bg  = (const float*)d_in[10];
    float* out = (float*)d_out;

    cudaFuncSetAttribute(gemm1_mma, cudaFuncAttributeMaxDynamicSharedMemorySize, NSTAGE * STG);
    cudaFuncSetAttribute(gemm2_mma, cudaFuncAttributeMaxDynamicSharedMemorySize, NSTAGE * STG);

    dim3 tb(32, 32);
    pack_w1_all<<<dim3(16, 32, 4), tb>>>(Wzf, Whf, Wzs, Whs);
    pack_wg<<<dim3(32, 32), tb>>>(Wg);
    convert_x16<<<(M_ * DIN / 4) / 256, 256>>>((const float4*)x, bzf, bhf, bzs, bhs);

    gemm1_mma<<<dim3(N1 / 128, M_ / 128), 256, NSTAGE * STG>>>();

    scan_phase1<<<dim3(8, NCHUNK), 256>>>();
    scan_phase2<<<LANES / 256, 256>>>();
    scan_phase3<<<dim3(8, NCHUNK), 256>>>();

    gemm2_mma<<<dim3(NC / 128, M_ / 128), 256, NSTAGE * STG>>>(bg, out);
}